// round 2
// baseline (speedup 1.0000x reference)
#include <cuda_runtime.h>
#include <math.h>

#define IN_F   512
#define HID    256
#define BATCH  1024

// Precomputed edge masks: bit set = "normal edge" (take x), clear = no_edge.
__device__ unsigned int g_mask0[HID * (IN_F / 32)];  // [256][16]
__device__ unsigned int g_mask1[IN_F * (HID / 32)];  // [512][8]

// ---------------------------------------------------------------------------
// Kernel 1: build bitmasks from (logits, u). One thread per edge, ballot-pack.
// argmax_e softmax(logits+g) == argmax_e (logits+g); tie -> e=0.
// Fast path logits equal: g monotone in clipped u  =>  compare u directly.
// ---------------------------------------------------------------------------
__global__ __launch_bounds__(256)
void mask_kernel(const float* __restrict__ logits0, const float* __restrict__ u0,
                 const float* __restrict__ logits1, const float* __restrict__ u1)
{
    int g = blockIdx.x * blockDim.x + threadIdx.x;   // 0 .. 262143
    const float* L;
    const float* U;
    unsigned int* M;
    int idx;
    if (g < HID * IN_F) { L = logits0; U = u0; M = g_mask0; idx = g; }
    else                { L = logits1; U = u1; M = g_mask1; idx = g - HID * IN_F; }

    float2 l = reinterpret_cast<const float2*>(L)[idx];
    float2 u = reinterpret_cast<const float2*>(U)[idx];

    const float LO = 1e-10f;
    const float HI = 1.0f - 1e-10f;   // == 1.0f in fp32, same as JAX's clip bound
    float ca = fminf(fmaxf(u.x, LO), HI);
    float cb = fminf(fmaxf(u.y, LO), HI);

    bool pred;
    if (l.x == l.y) {
        pred = cb > ca;                       // monotone shortcut
    } else {
        float g0 = -logf(-logf(ca));
        float g1 = -logf(-logf(cb));
        pred = (l.y + g1) > (l.x + g0);
    }

    unsigned bal = __ballot_sync(0xFFFFFFFFu, pred);
    if ((threadIdx.x & 31) == 0) M[idx >> 5] = bal;
}

// ---------------------------------------------------------------------------
// Kernel 2: fused two-layer evaluation, one block per batch row.
// Counting sort (values uniform in [0,1); x*512 and h*256 are exact power-of-2
// scalings, floor is monotone -> bucket order == value order; intra-bucket
// ties resolved by exact-value rescan at probe time).
//   1) counting-sort x row ascending by bucket
//   2) thread t (= hidden unit t) probes sorted order for first masked hit
//      -> exact min via tie-group (same-bucket) rescan
//   3) counting-sort h descending, probe for layer-1 max (2 outputs/thread)
// ---------------------------------------------------------------------------
__global__ __launch_bounds__(256)
void row_kernel(const float* __restrict__ x, float* __restrict__ out)
{
    __shared__ unsigned cnt[IN_F];    // counts, then exclusive offsets
    __shared__ unsigned skey[IN_F];   // sorted keys: (bucket<<9)|idx
    __shared__ float    sval[IN_F];   // exact x row
    __shared__ float    shv[HID];     // exact h row
    __shared__ unsigned wsum[8];      // per-warp scan totals

    const int b    = blockIdx.x;
    const int t    = threadIdx.x;     // 0..255
    const int lane = t & 31;
    const int w    = t >> 5;

    // ================= layer 0: counting sort of x (512 -> 512 buckets) ====
    cnt[t] = 0; cnt[t + 256] = 0;
    float v0 = x[b * IN_F + t];
    float v1 = x[b * IN_F + t + 256];
    sval[t] = v0; sval[t + 256] = v1;
    __syncthreads();

    int b0 = min((int)(v0 * 512.0f), 511);   // exact scaling -> monotone bucket
    int b1 = min((int)(v1 * 512.0f), 511);
    unsigned r0 = atomicAdd(&cnt[b0], 1u);   // rank within bucket
    unsigned r1 = atomicAdd(&cnt[b1], 1u);
    __syncthreads();

    // exclusive scan of 512 counts: thread t owns buckets 2t, 2t+1
    unsigned c0 = cnt[2 * t], c1 = cnt[2 * t + 1];
    unsigned s  = c0 + c1, sc = s;
#pragma unroll
    for (int d = 1; d < 32; d <<= 1) {
        unsigned o = __shfl_up_sync(0xFFFFFFFFu, sc, d);
        if (lane >= d) sc += o;
    }
    if (lane == 31) wsum[w] = sc;
    __syncthreads();                         // all cnt reads done; wsum ready
    unsigned wexcl = 0;
#pragma unroll
    for (int i = 0; i < 8; i++) if (i < w) wexcl += wsum[i];
    unsigned excl = wexcl + (sc - s);        // exclusive offset of bucket 2t
    cnt[2 * t]     = excl;
    cnt[2 * t + 1] = excl + c0;
    __syncthreads();

    // scatter keys into sorted positions
    skey[cnt[b0] + r0] = ((unsigned)b0 << 9) | (unsigned)t;
    skey[cnt[b1] + r1] = ((unsigned)b1 << 9) | (unsigned)(t + 256);
    __syncthreads();

    // ---- layer 0 probe: thread t owns hidden unit o = t ----
    const unsigned* __restrict__ m0 = g_mask0 + t * (IN_F / 32);
    float h = 1.0f;                          // default: no selected edge
    for (int k = 0; k < IN_F; k++) {
        unsigned key = skey[k];
        unsigned i   = key & 511u;
        if ((m0[i >> 5] >> (i & 31)) & 1u) {
            h = sval[i];
            unsigned qb = key >> 9;          // exact-min rescan of same bucket
            for (int k2 = k + 1; k2 < IN_F; k2++) {
                unsigned key2 = skey[k2];
                if ((key2 >> 9) != qb) break;
                unsigned i2 = key2 & 511u;
                if ((m0[i2 >> 5] >> (i2 & 31)) & 1u) h = fminf(h, sval[i2]);
            }
            break;
        }
    }
    __syncthreads();                         // probes done before smem reuse

    // ================= layer 1: counting sort of h (256 -> 256 buckets, desc)
    shv[t] = h;
    cnt[t] = 0;
    __syncthreads();

    int hb = min((int)(h * 256.0f), 255);
    int bd = 255 - hb;                       // descending order
    unsigned rr = atomicAdd(&cnt[bd], 1u);
    __syncthreads();

    unsigned c = cnt[t], scn = c;
#pragma unroll
    for (int d = 1; d < 32; d <<= 1) {
        unsigned o = __shfl_up_sync(0xFFFFFFFFu, scn, d);
        if (lane >= d) scn += o;
    }
    if (lane == 31) wsum[w] = scn;
    __syncthreads();
    unsigned wex = 0;
#pragma unroll
    for (int i = 0; i < 8; i++) if (i < w) wex += wsum[i];
    cnt[t] = wex + scn - c;                  // exclusive offset of bucket t
    __syncthreads();

    skey[cnt[bd] + rr] = ((unsigned)bd << 9) | (unsigned)t;
    __syncthreads();

    // ---- layer 1 probe: thread t owns outputs o = t and t + 256 ----
#pragma unroll
    for (int half = 0; half < 2; half++) {
        int o = t + half * 256;
        const unsigned* __restrict__ m1 = g_mask1 + o * (HID / 32);
        float r = 0.0f;                      // default: no selected edge
        for (int k = 0; k < HID; k++) {
            unsigned key = skey[k];
            unsigned j   = key & 511u;
            if ((m1[j >> 5] >> (j & 31)) & 1u) {
                r = shv[j];
                unsigned qb = key >> 9;      // exact-max rescan of same bucket
                for (int k2 = k + 1; k2 < HID; k2++) {
                    unsigned key2 = skey[k2];
                    if ((key2 >> 9) != qb) break;
                    unsigned j2 = key2 & 511u;
                    if ((m1[j2 >> 5] >> (j2 & 31)) & 1u) r = fmaxf(r, shv[j2]);
                }
                break;
            }
        }
        out[b * IN_F + o] = r;
    }
}

// ---------------------------------------------------------------------------
// kernel_launch: graph-capturable, allocation-free.
// Input order (metadata): x, logits0, u0, logits1, u1. Output: float32 [1024,512].
// ---------------------------------------------------------------------------
extern "C" void kernel_launch(void* const* d_in, const int* in_sizes, int n_in,
                              void* d_out, int out_size)
{
    const float* x       = (const float*)d_in[0];
    const float* logits0 = (const float*)d_in[1];
    const float* u0      = (const float*)d_in[2];
    const float* logits1 = (const float*)d_in[3];
    const float* u1      = (const float*)d_in[4];
    float* out = (float*)d_out;

    mask_kernel<<<(HID * IN_F * 2) / 256, 256>>>(logits0, u0, logits1, u1);
    row_kernel<<<BATCH, 256>>>(x, out);
}

// round 3
// speedup vs baseline: 5.0261x; 5.0261x over previous
#include <cuda_runtime.h>
#include <math.h>

#define IN_F   512
#define HID    256
#define BATCH  1024

// Precomputed edge masks: bit set = "normal edge" (take x), clear = no_edge.
__device__ unsigned int g_mask0[HID * (IN_F / 32)];  // [256][16]
__device__ unsigned int g_mask1[IN_F * (HID / 32)];  // [512][8]

// ---------------------------------------------------------------------------
// Kernel 1: build bitmasks from (logits, u). One thread per edge, ballot-pack.
// ---------------------------------------------------------------------------
__global__ __launch_bounds__(256)
void mask_kernel(const float* __restrict__ logits0, const float* __restrict__ u0,
                 const float* __restrict__ logits1, const float* __restrict__ u1)
{
    int g = blockIdx.x * blockDim.x + threadIdx.x;   // 0 .. 262143
    const float* L;
    const float* U;
    unsigned int* M;
    int idx;
    if (g < HID * IN_F) { L = logits0; U = u0; M = g_mask0; idx = g; }
    else                { L = logits1; U = u1; M = g_mask1; idx = g - HID * IN_F; }

    float2 l = reinterpret_cast<const float2*>(L)[idx];
    float2 u = reinterpret_cast<const float2*>(U)[idx];

    const float LO = 1e-10f;
    const float HI = 1.0f - 1e-10f;
    float ca = fminf(fmaxf(u.x, LO), HI);
    float cb = fminf(fmaxf(u.y, LO), HI);

    bool pred;
    if (l.x == l.y) {
        pred = cb > ca;                       // gumbel monotone in clipped u
    } else {
        float g0 = -logf(-logf(ca));
        float g1 = -logf(-logf(cb));
        pred = (l.y + g1) > (l.x + g0);
    }

    unsigned bal = __ballot_sync(0xFFFFFFFFu, pred);
    if ((threadIdx.x & 31) == 0) M[idx >> 5] = bal;
}

// ---------------------------------------------------------------------------
// Kernel 2: fused two-layer evaluation, one block per batch row.
//   Layer 0 (min over selected x): counting sort (x uniform -> ~1 elem/bucket),
//   probe sorted order for first masked hit, exact-min rescan of tie bucket.
//   Layer 1 (max over selected h): h is heavily clustered near 0, so bucket
//   sorts degenerate. Instead: exact rank-by-comparison sort with unique keys
//   (hbits>>7)<<8 | idx  -> permutation, no big tie groups, no divergence.
// ---------------------------------------------------------------------------
__global__ __launch_bounds__(256)
void row_kernel(const float* __restrict__ x, float* __restrict__ out)
{
    __shared__ unsigned cnt[IN_F];    // counts, then exclusive offsets
    __shared__ unsigned skey[IN_F];   // sorted keys
    __shared__ float    sval[IN_F];   // exact x row
    __shared__ float    shv[HID];     // exact h row
    __shared__ unsigned hkey[HID];    // layer-1 rank keys
    __shared__ unsigned wsum[8];

    const int b    = blockIdx.x;
    const int t    = threadIdx.x;     // 0..255
    const int lane = t & 31;
    const int w    = t >> 5;

    // ================= layer 0: counting sort of x (512 -> 512 buckets) ====
    cnt[t] = 0; cnt[t + 256] = 0;
    float v0 = x[b * IN_F + t];
    float v1 = x[b * IN_F + t + 256];
    sval[t] = v0; sval[t + 256] = v1;
    __syncthreads();

    int b0 = min((int)(v0 * 512.0f), 511);   // exact pow2 scaling -> monotone
    int b1 = min((int)(v1 * 512.0f), 511);
    unsigned r0 = atomicAdd(&cnt[b0], 1u);
    unsigned r1 = atomicAdd(&cnt[b1], 1u);
    __syncthreads();

    // exclusive scan of 512 counts: thread t owns buckets 2t, 2t+1
    unsigned c0 = cnt[2 * t], c1 = cnt[2 * t + 1];
    unsigned s  = c0 + c1, sc = s;
#pragma unroll
    for (int d = 1; d < 32; d <<= 1) {
        unsigned o = __shfl_up_sync(0xFFFFFFFFu, sc, d);
        if (lane >= d) sc += o;
    }
    if (lane == 31) wsum[w] = sc;
    __syncthreads();
    unsigned wexcl = 0;
#pragma unroll
    for (int i = 0; i < 8; i++) if (i < w) wexcl += wsum[i];
    unsigned excl = wexcl + (sc - s);
    cnt[2 * t]     = excl;
    cnt[2 * t + 1] = excl + c0;
    __syncthreads();

    skey[cnt[b0] + r0] = ((unsigned)b0 << 9) | (unsigned)t;
    skey[cnt[b1] + r1] = ((unsigned)b1 << 9) | (unsigned)(t + 256);
    __syncthreads();

    // ---- layer 0 probe: thread t owns hidden unit o = t ----
    const unsigned* __restrict__ m0 = g_mask0 + t * (IN_F / 32);
    float h = 1.0f;
    for (int k = 0; k < IN_F; k++) {
        unsigned key = skey[k];
        unsigned i   = key & 511u;
        if ((m0[i >> 5] >> (i & 31)) & 1u) {
            h = sval[i];
            unsigned qb = key >> 9;          // exact-min rescan of tie bucket
            for (int k2 = k + 1; k2 < IN_F; k2++) {
                unsigned key2 = skey[k2];
                if ((key2 >> 9) != qb) break;
                unsigned i2 = key2 & 511u;
                if ((m0[i2 >> 5] >> (i2 & 31)) & 1u) h = fminf(h, sval[i2]);
            }
            break;
        }
    }
    __syncthreads();                         // probes done before smem reuse

    // ========== layer 1: exact rank sort of h (descending, unique keys) ====
    shv[t] = h;
    unsigned mykey = ((__float_as_uint(h) >> 7) << 8) | (unsigned)t;  // 31 bits
    hkey[t] = mykey;
    __syncthreads();

    int rank = 0;
    const uint4* hk4 = (const uint4*)hkey;
#pragma unroll 8
    for (int j = 0; j < HID / 4; j++) {      // LDS.128 broadcast, no divergence
        uint4 k4 = hk4[j];
        rank += (int)(k4.x > mykey) + (int)(k4.y > mykey)
              + (int)(k4.z > mykey) + (int)(k4.w > mykey);
    }
    skey[rank] = mykey;                      // rank = #greater -> descending
    __syncthreads();

    // ---- layer 1 probe: thread t owns outputs o = t and t + 256 ----
#pragma unroll
    for (int half = 0; half < 2; half++) {
        int o = t + half * 256;
        const unsigned* __restrict__ m1 = g_mask1 + o * (HID / 32);
        float r = 0.0f;
        for (int k = 0; k < HID; k++) {
            unsigned key = skey[k];
            unsigned j   = key & 255u;
            if ((m1[j >> 5] >> (j & 31)) & 1u) {
                r = shv[j];
                unsigned qb = key >> 8;      // same (hbits>>7) group: rescan
                for (int k2 = k + 1; k2 < HID; k2++) {
                    unsigned key2 = skey[k2];
                    if ((key2 >> 8) != qb) break;
                    unsigned j2 = key2 & 255u;
                    if ((m1[j2 >> 5] >> (j2 & 31)) & 1u) r = fmaxf(r, shv[j2]);
                }
                break;
            }
        }
        out[b * IN_F + o] = r;
    }
}

// ---------------------------------------------------------------------------
// kernel_launch: graph-capturable, allocation-free.
// Inputs: x, logits0, u0, logits1, u1. Output: float32 [1024,512].
// ---------------------------------------------------------------------------
extern "C" void kernel_launch(void* const* d_in, const int* in_sizes, int n_in,
                              void* d_out, int out_size)
{
    const float* x       = (const float*)d_in[0];
    const float* logits0 = (const float*)d_in[1];
    const float* u0      = (const float*)d_in[2];
    const float* logits1 = (const float*)d_in[3];
    const float* u1      = (const float*)d_in[4];
    float* out = (float*)d_out;

    mask_kernel<<<(HID * IN_F * 2) / 256, 256>>>(logits0, u0, logits1, u1);
    row_kernel<<<BATCH, 256>>>(x, out);
}